// round 16
// baseline (speedup 1.0000x reference)
#include <cuda_runtime.h>

// ----------------------------------------------------------------------------
// Shapes (fixed by the problem):
//  scan1: (8, 16384, 1)  -> x1 (8,1,16384) (same memory since CIN=1)
//  f0: (8, 64, 8192)   enc0 k3 s2
//  f1: (8,128, 4096)   enc1 k3 s2
//  f2: (8,256, 2048)   enc2 k3 s2
//  feat: (8, 11, 2048) banded correlation (D=5, K=3)
//  cat1: (8,139->144, 4096) = [f1 ; up(feat)]
//  up1: (8,128, 4096)  dec1 k3 s1
//  cat0: (8,192, 8192) = [f0 ; up(up1)]
//  up0: (8,128, 8192)  dec0 k3 s1
//  flow: (8,2,16384)   k1 over [x1 ; up(up0)]  -> out (8,16384,2)
// Every conv is followed by training-mode BatchNorm (biased batch stats over
// (B,L)) and LeakyReLU(0.01).
// ----------------------------------------------------------------------------

#define BATCH 8

// Scratch buffers: __device__ globals (zero-initialized at module load).
// Padding regions (cat1 channels 139..143, g_wdec1 ci 139..143) are NEVER
// written, so they remain zero across every launch/replay.
__device__ float g_f0  [BATCH * 64  * 8192];
__device__ float g_f1  [BATCH * 128 * 4096];
__device__ float g_f2  [BATCH * 256 * 2048];
__device__ float g_feat[BATCH * 11  * 2048];
__device__ float g_cat1[BATCH * 144 * 4096];
__device__ float g_up1 [BATCH * 128 * 4096];
__device__ float g_cat0[BATCH * 192 * 8192];
__device__ float g_up0 [BATCH * 128 * 8192];
__device__ float g_flow[BATCH * 2   * 16384];
__device__ float g_wdec1[128 * 144 * 3];
__device__ float g_sum  [6 * 256];
__device__ float g_sumsq[6 * 256];
__device__ float g_scale[256];
__device__ float g_shift[256];

__device__ __forceinline__ float* buf_ptr(int sel) {
    switch (sel) {
        case 0: return g_f0;
        case 1: return g_f1;
        case 2: return g_f2;
        case 3: return g_cat1;
        case 4: return g_cat0;
        case 5: return g_up1;
        default: return g_up0;
    }
}

__device__ __forceinline__ float warp_sum(float v) {
    #pragma unroll
    for (int o = 16; o; o >>= 1) v += __shfl_xor_sync(0xffffffffu, v, o);
    return v;
}

// ---------------------------------------------------------------- stats zero
__global__ void zero_stats() {
    int t = blockIdx.x * blockDim.x + threadIdx.x;
    if (t < 6 * 256) { g_sum[t] = 0.f; g_sumsq[t] = 0.f; }
}

// --------------------------------------------------- dec1 weight zero-padding
// w: (128, 139, 3) -> g_wdec1: (128, 144, 3), pad channels stay zero (init).
__global__ void pad_dec1_w(const float* __restrict__ w) {
    int idx = blockIdx.x * blockDim.x + threadIdx.x;
    if (idx >= 128 * 139 * 3) return;
    int k  = idx % 3;
    int r  = idx / 3;
    int ci = r % 139;
    int co = r / 139;
    g_wdec1[(co * 144 + ci) * 3 + k] = w[idx];
}

// -------------------------------------------------------------- enc0 (Cin=1)
// y[b,co,i] = bias + sum_k w[co,0,k] * x[b, 2i + k - 1]  (zero pad)
__global__ __launch_bounds__(256)
void enc0_pass1(const float* __restrict__ x, const float* __restrict__ w,
                const float* __restrict__ bias) {
    __shared__ float rs, rq;
    const int co = blockIdx.y, b = blockIdx.z;
    const int i = blockIdx.x * 256 + threadIdx.x;      // Lout = 8192
    if (threadIdx.x == 0) { rs = 0.f; rq = 0.f; }
    __syncthreads();
    float w0 = __ldg(w + co * 3 + 0);
    float w1 = __ldg(w + co * 3 + 1);
    float w2 = __ldg(w + co * 3 + 2);
    const float* xb = x + (size_t)b * 16384;
    int p = 2 * i - 1;
    float v0 = (p >= 0) ? xb[p] : 0.f;
    float v1 = xb[2 * i];
    float v2 = xb[2 * i + 1];                          // 2i+1 <= 16383 always
    float a = __ldg(bias + co) + w0 * v0 + w1 * v1 + w2 * v2;
    g_f0[(size_t)(b * 64 + co) * 8192 + i] = a;
    float s = warp_sum(a), q = warp_sum(a * a);
    if ((threadIdx.x & 31) == 0) { atomicAdd(&rs, s); atomicAdd(&rq, q); }
    __syncthreads();
    if (threadIdx.x == 0) {
        atomicAdd(&g_sum[co], rs);
        atomicAdd(&g_sumsq[co], rq);
    }
}

// ----------------------------------------------------------- generic conv1d
// Tile: 64 cout x 64 i per block (256 threads, 4co x 4i register tile).
// x staged in smem in 16-channel chunks; weights staged as [ci][k][co] for
// float4 broadcast loads. Also accumulates per-channel sum / sum^2 (pre-BN).
template<int K, int STRIDE>
__global__ __launch_bounds__(256)
void conv_pass1(int xsel, const float* __restrict__ wext, int use_wpad,
                const float* __restrict__ bias, int ysel,
                int Cin, int Lin, int Cout, int Lout, int stat_off) {
    constexpr int TI  = 64;
    constexpr int TCO = 64;
    constexpr int CC  = 16;
    constexpr int XS  = TI * STRIDE + K - 1;       // 66 (s1) / 130 (s2)
    constexpr int XSP = (XS + 3) & ~3;             // float4-aligned rows
    constexpr int NX  = 3 * STRIDE + K;            // 6 (s1) / 9 (s2)

    __shared__ __align__(16) float x_s[CC * XSP];
    __shared__ __align__(16) float w_s[CC * K * TCO];
    __shared__ float red_s[TCO];
    __shared__ float red_q[TCO];

    const float* __restrict__ x = buf_ptr(xsel);
    float*       __restrict__ y = buf_ptr(ysel);
    const float* __restrict__ w = use_wpad ? (const float*)g_wdec1 : wext;

    const int tid = threadIdx.x;
    const int b = blockIdx.z;
    const int co_base = blockIdx.y * TCO;
    const int i0 = blockIdx.x * TI;
    const int gx0 = i0 * STRIDE - (K - 1) / 2;

    if (tid < TCO) { red_s[tid] = 0.f; red_q[tid] = 0.f; }

    const int ti = tid & 15;
    const int tc = tid >> 4;
    const int il0 = ti * 4;

    float acc[4][4];
    #pragma unroll
    for (int a = 0; a < 4; a++)
        #pragma unroll
        for (int i = 0; i < 4; i++) acc[a][i] = 0.f;

    const int nchunks = Cin / CC;
    for (int ch = 0; ch < nchunks; ch++) {
        const int c0 = ch * CC;
        __syncthreads();
        // stage x tile (zero-padded at sequence borders)
        for (int e = tid; e < CC * XS; e += 256) {
            int cc = e / XS, p = e - cc * XS;
            int g = gx0 + p;
            float v = 0.f;
            if (g >= 0 && g < Lin)
                v = x[(size_t)(b * Cin + c0 + cc) * Lin + g];
            x_s[cc * XSP + p] = v;
        }
        // stage weights as [cc][k][co]
        for (int e = tid; e < TCO * CC * K; e += 256) {
            int co = e / (CC * K);
            int r  = e - co * (CC * K);
            int cc = r / K;
            int k  = r - cc * K;
            w_s[(cc * K + k) * TCO + co] =
                w[(size_t)((co_base + co) * Cin + c0 + cc) * K + k];
        }
        __syncthreads();

        #pragma unroll 2
        for (int cc = 0; cc < CC; cc++) {
            const float* xp = &x_s[cc * XSP + il0 * STRIDE];
            float xr[NX];
            float4 t0 = *(const float4*)xp;
            xr[0] = t0.x; xr[1] = t0.y; xr[2] = t0.z; xr[3] = t0.w;
            if constexpr (NX == 6) {
                float2 t1 = *(const float2*)(xp + 4);
                xr[4] = t1.x; xr[5] = t1.y;
            } else {
                float4 t1 = *(const float4*)(xp + 4);
                xr[4] = t1.x; xr[5] = t1.y; xr[6] = t1.z; xr[7] = t1.w;
                xr[8] = xp[8];
            }
            float4 wv[K];
            #pragma unroll
            for (int k = 0; k < K; k++)
                wv[k] = *(const float4*)&w_s[(cc * K + k) * TCO + tc * 4];
            #pragma unroll
            for (int ii = 0; ii < 4; ii++) {
                #pragma unroll
                for (int k = 0; k < K; k++) {
                    float xv = xr[ii * STRIDE + k];
                    acc[0][ii] = fmaf(xv, wv[k].x, acc[0][ii]);
                    acc[1][ii] = fmaf(xv, wv[k].y, acc[1][ii]);
                    acc[2][ii] = fmaf(xv, wv[k].z, acc[2][ii]);
                    acc[3][ii] = fmaf(xv, wv[k].w, acc[3][ii]);
                }
            }
        }
    }

    #pragma unroll
    for (int c4 = 0; c4 < 4; c4++) {
        int co = co_base + tc * 4 + c4;
        float bv = __ldg(bias + co);
        float4 v;
        v.x = acc[c4][0] + bv; v.y = acc[c4][1] + bv;
        v.z = acc[c4][2] + bv; v.w = acc[c4][3] + bv;
        *(float4*)&y[(size_t)(b * Cout + co) * Lout + i0 + il0] = v;
        float s = v.x + v.y + v.z + v.w;
        float q = v.x * v.x + v.y * v.y + v.z * v.z + v.w * v.w;
        atomicAdd(&red_s[tc * 4 + c4], s);
        atomicAdd(&red_q[tc * 4 + c4], q);
    }
    __syncthreads();
    if (tid < TCO) {
        atomicAdd(&g_sum[stat_off + co_base + tid], red_s[tid]);
        atomicAdd(&g_sumsq[stat_off + co_base + tid], red_q[tid]);
    }
}

// --------------------------------------------------------------- BN finalize
// scale = gamma * rsqrt(var + eps), shift = beta - mean * scale
__global__ void bn_finalize(const float* __restrict__ g,
                            const float* __restrict__ be,
                            int C, float inv_n, int stat_off) {
    int c = threadIdx.x;
    if (c < C) {
        float m = g_sum[stat_off + c] * inv_n;
        float v = g_sumsq[stat_off + c] * inv_n - m * m;
        if (v < 0.f) v = 0.f;
        float s = __ldg(g + c) * rsqrtf(v + 1e-5f);
        g_scale[c] = s;
        g_shift[c] = fmaf(-m, s, __ldg(be + c));
    }
}

// ---------------------------------------------------- BN apply + LeakyReLU
__global__ __launch_bounds__(256)
void bn_apply(int sel, int C, int L, int total) {
    int idx = blockIdx.x * 256 + threadIdx.x;
    if (idx >= total) return;
    float* y = buf_ptr(sel);
    int c = (idx / L) % C;
    float v = fmaf(y[idx], g_scale[c], g_shift[c]);
    y[idx] = (v >= 0.f) ? v : 0.01f * v;
}

// --------------------------------------------------------- banded correlation
// corr[b,d,i] = sum_{c,kk} f2[b,c,cl(i+kk-1)] * f2[b,c,cl(cl(i+d)+kk-1)]
// Clamping is resolved at smem-load time: s[p] = f2[clamp(gbase+p)], so all
// inner indices are plain relative offsets.
__global__ __launch_bounds__(128)
void fusion_kernel() {
    constexpr int N = 2048, CB = 64, W = 140;      // 128 + 2*6 halo
    __shared__ float s[CB * W];
    const int b = blockIdx.y;
    const int il = threadIdx.x;
    const int i0 = blockIdx.x * 128;
    const int gbase = i0 - 6;
    const int gi = i0 + il;

    float acc[11];
    #pragma unroll
    for (int d = 0; d < 11; d++) acc[d] = 0.f;
    int jb[11];
    #pragma unroll
    for (int d = 0; d < 11; d++) {
        int j = gi + d - 5;
        j = j < 0 ? 0 : (j > N - 1 ? N - 1 : j);
        jb[d] = j - gbase;
    }
    const int ab = il + 6;

    for (int c0 = 0; c0 < 256; c0 += CB) {
        __syncthreads();
        for (int e = il; e < CB * W; e += 128) {
            int cc = e / W, p = e - cc * W;
            int g = gbase + p;
            g = g < 0 ? 0 : (g > N - 1 ? N - 1 : g);
            s[cc * W + p] = g_f2[(size_t)(b * 256 + c0 + cc) * N + g];
        }
        __syncthreads();
        for (int cc = 0; cc < CB; cc++) {
            const float* row = &s[cc * W];
            float a0 = row[ab - 1], a1 = row[ab], a2 = row[ab + 1];
            #pragma unroll
            for (int d = 0; d < 11; d++) {
                const float* r = row + jb[d];
                acc[d] += a0 * r[-1] + a1 * r[0] + a2 * r[1];
            }
        }
    }
    #pragma unroll
    for (int d = 0; d < 11; d++)
        g_feat[(size_t)(b * 11 + d) * N + gi] = acc[d];
}

// ------------------------------------------------------- concat + upsample
__global__ __launch_bounds__(256)
void build_cat1() {
    const int per = 139 * 4096;
    int idx = blockIdx.x * 256 + threadIdx.x;
    if (idx >= BATCH * per) return;
    int b = idx / per;
    int r = idx - b * per;
    int c = r / 4096;
    int i = r - c * 4096;
    float v = (c < 128)
        ? g_f1[(size_t)(b * 128 + c) * 4096 + i]
        : g_feat[(size_t)(b * 11 + (c - 128)) * 2048 + (i >> 1)];
    g_cat1[(size_t)(b * 144 + c) * 4096 + i] = v;   // ch 139..143 stay zero
}

__global__ __launch_bounds__(256)
void build_cat0() {
    const int per = 192 * 8192;
    int idx = blockIdx.x * 256 + threadIdx.x;
    if (idx >= BATCH * per) return;
    int b = idx / per;
    int r = idx - b * per;
    int c = r / 8192;
    int i = r - c * 8192;
    float v = (c < 64)
        ? g_f0[(size_t)(b * 64 + c) * 8192 + i]
        : g_up1[(size_t)(b * 128 + (c - 64)) * 4096 + (i >> 1)];
    g_cat0[(size_t)(b * 192 + c) * 8192 + i] = v;
}

// --------------------------------------------------- flow conv (k=1, Cout=2)
// input channels = [x1 (1ch) ; upsample(up0) (128ch)]
__global__ __launch_bounds__(256)
void flow_pass1(const float* __restrict__ x1, const float* __restrict__ w,
                const float* __restrict__ bias) {
    __shared__ float ws[258];
    __shared__ float red[4];
    const int tid = threadIdx.x;
    if (tid < 4) red[tid] = 0.f;
    for (int e = tid; e < 258; e += 256) ws[e] = w[e];
    __syncthreads();

    const int b = blockIdx.y;
    const int n = blockIdx.x * 256 + tid;          // 16384 total
    float xv = x1[(size_t)b * 16384 + n];
    float a0 = __ldg(bias + 0) + ws[0]   * xv;
    float a1 = __ldg(bias + 1) + ws[129] * xv;
    const float* u = g_up0 + (size_t)b * 128 * 8192 + (n >> 1);
    #pragma unroll 4
    for (int c = 0; c < 128; c++) {
        float v = u[(size_t)c * 8192];
        a0 = fmaf(ws[1 + c],   v, a0);
        a1 = fmaf(ws[130 + c], v, a1);
    }
    g_flow[(size_t)(b * 2 + 0) * 16384 + n] = a0;
    g_flow[(size_t)(b * 2 + 1) * 16384 + n] = a1;

    float s0 = warp_sum(a0), q0 = warp_sum(a0 * a0);
    float s1 = warp_sum(a1), q1 = warp_sum(a1 * a1);
    if ((tid & 31) == 0) {
        atomicAdd(&red[0], s0); atomicAdd(&red[1], q0);
        atomicAdd(&red[2], s1); atomicAdd(&red[3], q1);
    }
    __syncthreads();
    if (tid == 0) {
        atomicAdd(&g_sum[5 * 256 + 0],   red[0]);
        atomicAdd(&g_sumsq[5 * 256 + 0], red[1]);
        atomicAdd(&g_sum[5 * 256 + 1],   red[2]);
        atomicAdd(&g_sumsq[5 * 256 + 1], red[3]);
    }
}

// BN + LeakyReLU + transpose to (B, N, 2)
__global__ __launch_bounds__(256)
void flow_out(float* __restrict__ out) {
    int idx = blockIdx.x * 256 + threadIdx.x;      // B*N = 131072
    if (idx >= BATCH * 16384) return;
    int b = idx / 16384;
    int n = idx - b * 16384;
    float v0 = fmaf(g_flow[(size_t)(b * 2 + 0) * 16384 + n], g_scale[0], g_shift[0]);
    float v1 = fmaf(g_flow[(size_t)(b * 2 + 1) * 16384 + n], g_scale[1], g_shift[1]);
    v0 = (v0 >= 0.f) ? v0 : 0.01f * v0;
    v1 = (v1 >= 0.f) ? v1 : 0.01f * v1;
    reinterpret_cast<float2*>(out)[idx] = make_float2(v0, v1);
}

// ----------------------------------------------------------------------------
extern "C" void kernel_launch(void* const* d_in, const int* in_sizes, int n_in,
                              void* d_out, int out_size) {
    (void)in_sizes; (void)n_in; (void)out_size;
    const float* scan1 = (const float*)d_in[0];
    const float* e0w = (const float*)d_in[1];
    const float* e0b = (const float*)d_in[2];
    const float* e0g = (const float*)d_in[3];
    const float* e0be = (const float*)d_in[4];
    const float* e1w = (const float*)d_in[5];
    const float* e1b = (const float*)d_in[6];
    const float* e1g = (const float*)d_in[7];
    const float* e1be = (const float*)d_in[8];
    const float* e2w = (const float*)d_in[9];
    const float* e2b = (const float*)d_in[10];
    const float* e2g = (const float*)d_in[11];
    const float* e2be = (const float*)d_in[12];
    const float* d1w = (const float*)d_in[13];
    const float* d1b = (const float*)d_in[14];
    const float* d1g = (const float*)d_in[15];
    const float* d1be = (const float*)d_in[16];
    const float* d0w = (const float*)d_in[17];
    const float* d0b = (const float*)d_in[18];
    const float* d0g = (const float*)d_in[19];
    const float* d0be = (const float*)d_in[20];
    const float* fw  = (const float*)d_in[21];
    const float* fb  = (const float*)d_in[22];
    const float* fg  = (const float*)d_in[23];
    const float* fbe = (const float*)d_in[24];

    zero_stats<<<6, 256>>>();
    pad_dec1_w<<<(128 * 139 * 3 + 255) / 256, 256>>>(d1w);

    // enc0: (B,1,16384) -> f0 (B,64,8192)
    enc0_pass1<<<dim3(32, 64, 8), 256>>>(scan1, e0w, e0b);
    bn_finalize<<<1, 256>>>(e0g, e0be, 64, 1.0f / 65536.0f, 0);
    bn_apply<<<16384, 256>>>(0, 64, 8192, BATCH * 64 * 8192);

    // enc1: f0 -> f1 (B,128,4096)
    conv_pass1<3, 2><<<dim3(64, 2, 8), 256>>>(0, e1w, 0, e1b, 1,
                                              64, 8192, 128, 4096, 256);
    bn_finalize<<<1, 256>>>(e1g, e1be, 128, 1.0f / 32768.0f, 256);
    bn_apply<<<16384, 256>>>(1, 128, 4096, BATCH * 128 * 4096);

    // enc2: f1 -> f2 (B,256,2048)
    conv_pass1<3, 2><<<dim3(32, 4, 8), 256>>>(1, e2w, 0, e2b, 2,
                                              128, 4096, 256, 2048, 512);
    bn_finalize<<<1, 256>>>(e2g, e2be, 256, 1.0f / 16384.0f, 512);
    bn_apply<<<16384, 256>>>(2, 256, 2048, BATCH * 256 * 2048);

    // correlation -> feat (B,11,2048)
    fusion_kernel<<<dim3(16, 8), 128>>>();

    // dec1: [f1 ; up(feat)] (padded to 144 ch) -> up1 (B,128,4096)
    build_cat1<<<(BATCH * 139 * 4096 + 255) / 256, 256>>>();
    conv_pass1<3, 1><<<dim3(64, 2, 8), 256>>>(3, nullptr, 1, d1b, 5,
                                              144, 4096, 128, 4096, 768);
    bn_finalize<<<1, 256>>>(d1g, d1be, 128, 1.0f / 32768.0f, 768);
    bn_apply<<<16384, 256>>>(5, 128, 4096, BATCH * 128 * 4096);

    // dec0: [f0 ; up(up1)] (192 ch) -> up0 (B,128,8192)
    build_cat0<<<(BATCH * 192 * 8192 + 255) / 256, 256>>>();
    conv_pass1<3, 1><<<dim3(128, 2, 8), 256>>>(4, d0w, 0, d0b, 6,
                                               192, 8192, 128, 8192, 1024);
    bn_finalize<<<1, 256>>>(d0g, d0be, 128, 1.0f / 65536.0f, 1024);
    bn_apply<<<32768, 256>>>(6, 128, 8192, BATCH * 128 * 8192);

    // flow head (k=1, 129 -> 2) + BN + transpose out
    flow_pass1<<<dim3(64, 8), 256>>>(scan1, fw, fb);
    bn_finalize<<<1, 256>>>(fg, fbe, 2, 1.0f / 131072.0f, 1280);
    flow_out<<<512, 256>>>((float*)d_out);
}